// round 15
// baseline (speedup 1.0000x reference)
#include <cuda_runtime.h>
#include <cuda_bf16.h>
#include <math.h>
#include <stdint.h>

// Problem constants: B=2, H=16, L=2048, D=128, BLKQ=BLKK=64, topk=4
#define B_    2
#define H_    16
#define L_    2048
#define D_    128
#define BH    32
#define NBLK  32
#define TOPK  4
#define NPART 4

#define KPSTR 68     // u32 stride, k-pair-packed arrays
#define RPSTR 136    // u32 stride, row-pair-packed arrays
#define PSSTR 68     // u32 stride, per-block packed S (hi [0,32), lo [36,68))
#define WSTR  132    // f32 stride for k_M tiles

// ---------------- static device scratch ----------------
__device__ float g_qb[BH*NBLK*D_];
__device__ float g_kb[BH*NBLK*D_];
__device__ int   g_lut[BH*NBLK*TOPK];
__device__ float g_kvpart[(size_t)BH*NPART*D_*D_];
__device__ float g_kvsum[BH*D_*D_];
__device__ float g_ksum [BH*D_];
__device__ uint32_t g_Mh[BH*64*D_];   // M packed: bf16 hi plane (d-pair rows)
__device__ uint32_t g_Ml[BH*64*D_];   // M packed: bf16 lo plane
__device__ float g_lin[(size_t)BH*L_*D_];   // linear-branch output (incl. bias)

// ---------------- helpers ----------------
__device__ __forceinline__ void mma16(float c[4],
                                      uint32_t a0, uint32_t a1, uint32_t a2, uint32_t a3,
                                      uint32_t b0, uint32_t b1)
{
    asm volatile(
        "mma.sync.aligned.m16n8k16.row.col.f32.bf16.bf16.f32 "
        "{%0,%1,%2,%3},{%4,%5,%6,%7},{%8,%9},{%0,%1,%2,%3};\n"
        : "+f"(c[0]), "+f"(c[1]), "+f"(c[2]), "+f"(c[3])
        : "r"(a0), "r"(a1), "r"(a2), "r"(a3), "r"(b0), "r"(b1));
}

__device__ __forceinline__ void ldsm4(uint32_t addr,
                                      uint32_t& r0, uint32_t& r1, uint32_t& r2, uint32_t& r3)
{
    asm volatile("ldmatrix.sync.aligned.m8n8.x4.shared.b16 {%0,%1,%2,%3}, [%4];"
                 : "=r"(r0), "=r"(r1), "=r"(r2), "=r"(r3) : "r"(addr));
}

__device__ __forceinline__ uint32_t smem_u32(const void* p)
{
    uint32_t a;
    asm("{ .reg .u64 t; cvta.to.shared.u64 t, %1; cvt.u32.u64 %0, t; }" : "=r"(a) : "l"(p));
    return a;
}

// pack (x0, x1) -> hw = bf16(x1)<<16 | bf16(x0), lw = residuals
__device__ __forceinline__ void packpair(float x0, float x1, uint32_t& hw, uint32_t& lw)
{
    uint32_t h;
    asm("cvt.rn.bf16x2.f32 %0, %1, %2;" : "=r"(h) : "f"(x1), "f"(x0));
    float h0 = __uint_as_float(h << 16);
    float h1 = __uint_as_float(h & 0xFFFF0000u);
    uint32_t l;
    asm("cvt.rn.bf16x2.f32 %0, %1, %2;" : "=r"(l) : "f"(x1 - h1), "f"(x0 - h0));
    hw = h; lw = l;
}

__device__ __forceinline__ float bfhi(uint32_t w) { return __uint_as_float(w & 0xFFFF0000u); }
__device__ __forceinline__ float bflo(uint32_t w) { return __uint_as_float(w << 16); }

// ---------------- kernel 1: block means ----------------
__global__ void k_blockmean(const float* __restrict__ q, const float* __restrict__ k)
{
    int id    = blockIdx.x;
    int which = id >> 10;
    int rem   = id & 1023;
    const float* src = which ? k : q;
    float*       dst = which ? g_kb : g_qb;
    int d = threadIdx.x;
    const float* base = src + (size_t)rem * 64 * D_ + d;
    float s = 0.f;
#pragma unroll 8
    for (int r = 0; r < 64; r++) s += base[r * D_];
    dst[rem * D_ + d] = s * (1.0f / 64.0f);
}

// ---------------- kernel 2: top-4 selection ----------------
__global__ void k_topk()
{
    int id   = blockIdx.x;
    int bh   = id >> 5;
    int lane = threadIdx.x;
    const float4* q4 = (const float4*)(g_qb + id * D_);
    const float4* k4 = (const float4*)(g_kb + (bh * NBLK + lane) * D_);
    float s = 0.f;
#pragma unroll
    for (int d4 = 0; d4 < 32; d4++) {
        float4 a = q4[d4], b = k4[d4];
        s += a.x*b.x + a.y*b.y + a.z*b.z + a.w*b.w;
    }
    float val = s;
    for (int t = 0; t < TOPK; t++) {
        float m = val; int mi = lane;
#pragma unroll
        for (int o = 16; o > 0; o >>= 1) {
            float ov = __shfl_xor_sync(0xffffffffu, m,  o);
            int   oi = __shfl_xor_sync(0xffffffffu, mi, o);
            if (ov > m || (ov == m && oi < mi)) { m = ov; mi = oi; }
        }
        if (lane == 0)  g_lut[id * TOPK + t] = mi;
        if (lane == mi) val = -3.0e38f;
    }
}

// ---------------- kernel 3: sparse attention + g_lin add, streaming softmax ----------------
__global__ void __launch_bounds__(512, 2)
k_sparse(const float* __restrict__ q, const float* __restrict__ k,
         const float* __restrict__ v, float* __restrict__ out)
{
    extern __shared__ float sm[];
    uint32_t* Qh  = (uint32_t*)sm;        // 64*68
    uint32_t* Ql  = Qh + 64 * KPSTR;
    uint32_t* KVh = Ql + 64 * KPSTR;      // K: 64*68 = 4352 / V: 32*136 = 4352 u32
    uint32_t* KVl = KVh + 4352;
    uint32_t* Su  = KVl + 4352;           // packed S per block: 64 x 68
    float*    red = (float*)(Su + 64 * PSSTR);   // 512 floats rowsum reduce

    const uint32_t QhB  = smem_u32(Qh);
    const uint32_t QlB  = QhB + 64 * KPSTR * 4;
    const uint32_t KVhB = QlB + 64 * KPSTR * 4;
    const uint32_t KVlB = KVhB + 4352 * 4;
    const uint32_t SuB  = KVlB + 4352 * 4;

    int id = blockIdx.x;                  // bh*32 + qb
    int bh = id >> 5, qb = id & 31;
    int tid  = threadIdx.x;
    int warp = tid >> 5, lane = tid & 31;
    int g = lane >> 2, t = lane & 3;
    int wm = warp >> 2, wn = warp & 3;    // 4x4 warps
    const size_t bh_off = (size_t)bh * L_ * D_;
    const float scale = 0.088388347648318447f;   // 1/sqrt(128)

    // stage Q (scaled, packed k-pairs): 64 rows
    for (int i = tid; i < 64 * 32; i += 512) {
        int row = i >> 5, c4 = i & 31;
        float4 val = ((const float4*)(q + bh_off + (size_t)(qb * 64 + row) * D_))[c4];
        uint32_t h0, l0, h1, l1;
        packpair(val.x * scale, val.y * scale, h0, l0);
        packpair(val.z * scale, val.w * scale, h1, l1);
        *(uint2*)&Qh[row * KPSTR + 2 * c4] = make_uint2(h0, h1);
        *(uint2*)&Ql[row * KPSTR + 2 * c4] = make_uint2(l0, l1);
    }

    int blks[4];
#pragma unroll
    for (int tt = 0; tt < 4; tt++) blks[tt] = g_lut[id * TOPK + tt];

    // LDSM lane addresses
    const int r0 = wm * 16;
    uint32_t aAddrQ = (lane < 16 ? QhB : QlB) + (uint32_t)(r0 + (lane & 15)) * KPSTR * 4;
    const int rowB = wn * 16 + ((lane >> 4) << 3) + (lane & 7);
    uint32_t bArr  = (((lane >> 3) & 1) ? KVlB : KVhB);
    uint32_t bAddr = bArr + (uint32_t)rowB * KPSTR * 4;
    uint32_t aAddrS = SuB + ((uint32_t)(r0 + (lane & 15)) * PSSTR + (lane >= 16 ? 36u : 0u)) * 4;

    float o[4][4];
#pragma unroll
    for (int nt = 0; nt < 4; nt++)
#pragma unroll
        for (int c = 0; c < 4; c++) o[nt][c] = 0.f;
    float rs0 = 0.f, rs1 = 0.f;

    for (int pass = 0; pass < 4; pass++) {
        int blk = blks[pass];
        __syncthreads();
        for (int i = tid; i < 64 * 32; i += 512) {
            int row = i >> 5, c4 = i & 31;
            int gr  = blk * 64 + row;
            float4 val = ((const float4*)(k + bh_off + (size_t)gr * D_))[c4];
            uint32_t h0, l0, h1, l1;
            packpair(val.x, val.y, h0, l0);
            packpair(val.z, val.w, h1, l1);
            *(uint2*)&KVh[row * KPSTR + 2 * c4] = make_uint2(h0, h1);
            *(uint2*)&KVl[row * KPSTR + 2 * c4] = make_uint2(l0, l1);
        }
        __syncthreads();

        float acc[2][4];
#pragma unroll
        for (int nt = 0; nt < 2; nt++)
#pragma unroll
            for (int c = 0; c < 4; c++) acc[nt][c] = 0.f;
#pragma unroll
        for (int ks = 0; ks < 16; ks++) {
            uint32_t a0, a1, a2, a3;
            ldsm4(aAddrQ + ks * 16, a0, a1, a2, a3);
            uint32_t b0h, b0l, b1h, b1l;
            ldsm4(bAddr + ks * 16, b0h, b0l, b1h, b1l);
            mma16(acc[0], a0, a1, a2, a3, b0h, b0l);
            mma16(acc[0], a0, a1, a2, a3, b0l, b0h);
            mma16(acc[1], a0, a1, a2, a3, b1h, b1l);
            mma16(acc[1], a0, a1, a2, a3, b1l, b1h);
        }

#pragma unroll
        for (int nt = 0; nt < 2; nt++) {
            float e0 = __expf(acc[nt][0]), e1 = __expf(acc[nt][1]);
            float e2 = __expf(acc[nt][2]), e3 = __expf(acc[nt][3]);
            rs0 += e0 + e1;
            rs1 += e2 + e3;
            int pc = wn * 8 + nt * 4 + t;
            uint32_t hw, lw;
            packpair(e0, e1, hw, lw);
            Su[(r0 + g) * PSSTR + pc]      = hw;
            Su[(r0 + g) * PSSTR + 36 + pc] = lw;
            packpair(e2, e3, hw, lw);
            Su[(r0 + g + 8) * PSSTR + pc]      = hw;
            Su[(r0 + g + 8) * PSSTR + 36 + pc] = lw;
        }
        __syncthreads();
        for (int i = tid; i < 32 * 32; i += 512) {
            int m = i >> 5, dg = i & 31;
            int gr0 = blk * 64 + 2 * m;
            const float* vp = v + bh_off + (size_t)gr0 * D_;
            float4 v0 = ((const float4*)vp)[dg];
            float4 v1 = ((const float4*)(vp + D_))[dg];
            uint32_t hw0, lw0, hw1, lw1, hw2, lw2, hw3, lw3;
            packpair(v0.x, v1.x, hw0, lw0);
            packpair(v0.y, v1.y, hw1, lw1);
            packpair(v0.z, v1.z, hw2, lw2);
            packpair(v0.w, v1.w, hw3, lw3);
            *(uint4*)&KVh[m * RPSTR + 4 * dg] = make_uint4(hw0, hw1, hw2, hw3);
            *(uint4*)&KVl[m * RPSTR + 4 * dg] = make_uint4(lw0, lw1, lw2, lw3);
        }
        __syncthreads();
        int n0 = wn * 32 + g;
#pragma unroll
        for (int ks = 0; ks < 8; ks++) {
            int jp = ks * 4 + t;
            uint32_t a0, a1, a2, a3;
            ldsm4(aAddrS + ks * 16, a0, a1, a2, a3);
#pragma unroll
            for (int nt = 0; nt < 4; nt++) {
                int d = n0 + nt * 8;
                uint32_t bhw = KVh[jp * RPSTR + d];
                uint32_t blw = KVl[jp * RPSTR + d];
                mma16(o[nt], a0, a1, a2, a3, bhw, blw);
                mma16(o[nt], a0, a1, a2, a3, blw, bhw);
            }
        }
    }

#pragma unroll
    for (int o2 = 1; o2 <= 2; o2 <<= 1) {
        rs0 += __shfl_xor_sync(0xffffffffu, rs0, o2);
        rs1 += __shfl_xor_sync(0xffffffffu, rs1, o2);
    }
    if (t == 0) {
        red[(r0 + g) * 4 + wn]     = rs0;
        red[(r0 + g + 8) * 4 + wn] = rs1;
    }
    __syncthreads();
    float inv0 = 1.f / (red[(r0+g)*4+0] + red[(r0+g)*4+1]
                      + red[(r0+g)*4+2] + red[(r0+g)*4+3]);
    float inv1 = 1.f / (red[(r0+g+8)*4+0] + red[(r0+g+8)*4+1]
                      + red[(r0+g+8)*4+2] + red[(r0+g+8)*4+3]);
    float* op = out + bh_off + (size_t)(qb * 64) * D_;
    const float* lp = g_lin + bh_off + (size_t)(qb * 64) * D_;
    int r = r0 + g;
#pragma unroll
    for (int nt = 0; nt < 4; nt++) {
        int cc = wn * 32 + nt * 8 + 2 * t;
        float2 l0v = *(const float2*)&lp[r * D_ + cc];
        float2 l1v = *(const float2*)&lp[(r + 8) * D_ + cc];
        *(float2*)&op[r * D_ + cc] =
            make_float2(o[nt][0] * inv0 + l0v.x, o[nt][1] * inv0 + l0v.y);
        *(float2*)&op[(r + 8) * D_ + cc] =
            make_float2(o[nt][2] * inv1 + l1v.x, o[nt][3] * inv1 + l1v.y);
    }
}

// ---------------- kernel 4: kvsum/ksum partials (bf16-pair mma, 16 warps) ----------------
__global__ void __launch_bounds__(512, 1)
k_kv(const float* __restrict__ k, const float* __restrict__ v)
{
    extern __shared__ float sm[];
    uint32_t* PHh = (uint32_t*)sm;          // 32*136
    uint32_t* PHl = PHh + 32 * RPSTR;
    uint32_t* VVh = PHl + 32 * RPSTR;
    uint32_t* VVl = VVh + 32 * RPSTR;

    int bh   = blockIdx.x >> 2;
    int part = blockIdx.x & 3;
    int tid  = threadIdx.x;
    int warp = tid >> 5, lane = tid & 31;
    int g = lane >> 2, t = lane & 3;
    int wm = warp >> 2, wn = warp & 3;      // tile m32 (d) x n32 (e)
    const size_t bh_off = (size_t)bh * L_ * D_;

    float acc[2][4][4];
#pragma unroll
    for (int mt = 0; mt < 2; mt++)
#pragma unroll
        for (int nt = 0; nt < 4; nt++)
#pragma unroll
            for (int c = 0; c < 4; c++) acc[mt][nt][c] = 0.f;
    float ks_loc = 0.f;

    for (int ch = 0; ch < 8; ch++) {
        int l0 = part * 512 + ch * 64;
        __syncthreads();
#pragma unroll
        for (int pp = 0; pp < 2; pp++) {
            int m = warp * 2 + pp;
            size_t l = bh_off + (size_t)(l0 + 2 * m) * D_;
            float4 k0 = ((const float4*)(k + l))[lane];
            float4 k1 = ((const float4*)(k + l + D_))[lane];
            float mx0 = fmaxf(fmaxf(k0.x, k0.y), fmaxf(k0.z, k0.w));
            float mx1 = fmaxf(fmaxf(k1.x, k1.y), fmaxf(k1.z, k1.w));
#pragma unroll
            for (int o2 = 16; o2 > 0; o2 >>= 1) {
                mx0 = fmaxf(mx0, __shfl_xor_sync(0xffffffffu, mx0, o2));
                mx1 = fmaxf(mx1, __shfl_xor_sync(0xffffffffu, mx1, o2));
            }
            float e0x = __expf(k0.x - mx0), e0y = __expf(k0.y - mx0);
            float e0z = __expf(k0.z - mx0), e0w = __expf(k0.w - mx0);
            float e1x = __expf(k1.x - mx1), e1y = __expf(k1.y - mx1);
            float e1z = __expf(k1.z - mx1), e1w = __expf(k1.w - mx1);
            float s0 = e0x + e0y + e0z + e0w;
            float s1 = e1x + e1y + e1z + e1w;
#pragma unroll
            for (int o2 = 16; o2 > 0; o2 >>= 1) {
                s0 += __shfl_xor_sync(0xffffffffu, s0, o2);
                s1 += __shfl_xor_sync(0xffffffffu, s1, o2);
            }
            float i0 = 1.f / s0, i1 = 1.f / s1;
            uint32_t hw0, lw0, hw1, lw1, hw2, lw2, hw3, lw3;
            packpair(e0x * i0, e1x * i1, hw0, lw0);
            packpair(e0y * i0, e1y * i1, hw1, lw1);
            packpair(e0z * i0, e1z * i1, hw2, lw2);
            packpair(e0w * i0, e1w * i1, hw3, lw3);
            *(uint4*)&PHh[m * RPSTR + 4 * lane] = make_uint4(hw0, hw1, hw2, hw3);
            *(uint4*)&PHl[m * RPSTR + 4 * lane] = make_uint4(lw0, lw1, lw2, lw3);
            float4 v0 = ((const float4*)(v + l))[lane];
            float4 v1 = ((const float4*)(v + l + D_))[lane];
            packpair(v0.x, v1.x, hw0, lw0);
            packpair(v0.y, v1.y, hw1, lw1);
            packpair(v0.z, v1.z, hw2, lw2);
            packpair(v0.w, v1.w, hw3, lw3);
            *(uint4*)&VVh[m * RPSTR + 4 * lane] = make_uint4(hw0, hw1, hw2, hw3);
            *(uint4*)&VVl[m * RPSTR + 4 * lane] = make_uint4(lw0, lw1, lw2, lw3);
        }
        __syncthreads();
        if (tid < 128) {
            float s = 0.f;
#pragma unroll 8
            for (int m = 0; m < 32; m++) {
                uint32_t whi = PHh[m * RPSTR + tid];
                uint32_t wlo = PHl[m * RPSTR + tid];
                s += bfhi(whi) + bflo(whi) + bfhi(wlo) + bflo(wlo);
            }
            ks_loc += s;
        }
#pragma unroll
        for (int ks2 = 0; ks2 < 8; ks2++) {
            int lp = ks2 * 4 + t;
            uint32_t a[2][4];
#pragma unroll
            for (int mt = 0; mt < 2; mt++) {
                int r = wm * 32 + mt * 16 + g;
                a[mt][0] = PHh[lp * RPSTR + r];
                a[mt][1] = PHh[lp * RPSTR + r + 8];
                a[mt][2] = PHl[lp * RPSTR + r];
                a[mt][3] = PHl[lp * RPSTR + r + 8];
            }
#pragma unroll
            for (int nt = 0; nt < 4; nt++) {
                int n = wn * 32 + nt * 8 + g;
                uint32_t bhw = VVh[lp * RPSTR + n];
                uint32_t blw = VVl[lp * RPSTR + n];
#pragma unroll
                for (int mt = 0; mt < 2; mt++) {
                    mma16(acc[mt][nt], a[mt][0], a[mt][1], a[mt][2], a[mt][3], bhw, blw);
                    mma16(acc[mt][nt], a[mt][0], a[mt][1], a[mt][2], a[mt][3], blw, bhw);
                }
            }
        }
    }
    float* dst = g_kvpart + ((size_t)bh * NPART + part) * D_ * D_;
#pragma unroll
    for (int mt = 0; mt < 2; mt++)
#pragma unroll
        for (int nt = 0; nt < 4; nt++) {
            int d0 = wm * 32 + mt * 16 + g;
            int e0 = wn * 32 + nt * 8 + 2 * t;
            *(float2*)&dst[d0 * D_ + e0]       = make_float2(acc[mt][nt][0], acc[mt][nt][1]);
            *(float2*)&dst[(d0 + 8) * D_ + e0] = make_float2(acc[mt][nt][2], acc[mt][nt][3]);
        }
    if (tid < 128) atomicAdd(&g_ksum[bh * D_ + tid], ks_loc);
}

// ---------------- kernel 4b: reduce kv partials ----------------
__global__ void __launch_bounds__(256)
k_red()
{
    int bh = blockIdx.x >> 2, qr = blockIdx.x & 3;
    int tid = threadIdx.x;
#pragma unroll
    for (int j = 0; j < 4; j++) {
        int o = qr * 4096 + j * 1024 + tid * 4;
        float4 s = make_float4(0.f, 0.f, 0.f, 0.f);
#pragma unroll
        for (int p = 0; p < NPART; p++) {
            float4 w = *(const float4*)&g_kvpart[((size_t)bh * NPART + p) * D_ * D_ + o];
            s.x += w.x; s.y += w.y; s.z += w.z; s.w += w.w;
        }
        *(float4*)&g_kvsum[bh * D_ * D_ + o] = s;
    }
}

// ---------------- kernel 5: M = kvsum @ w_proj^T, emitted pre-packed ----------------
__global__ void __launch_bounds__(256)
k_M(const float* __restrict__ w)
{
    extern __shared__ float sm[];
    float* kvt = sm;
    float* wt  = sm + 128 * WSTR;
    int bh = blockIdx.x;
    int tid = threadIdx.x;
    const float* kv = g_kvsum + bh * D_ * D_;
    for (int idx = tid; idx < D_ * D_; idx += 256) {
        int d = idx >> 7, e = idx & 127;
        kvt[e * WSTR + d] = kv[idx];
        wt [e * WSTR + d] = w[idx];
    }
    __syncthreads();
    int dg = tid >> 4, eg = tid & 15;
    float acc[8][8];
#pragma unroll
    for (int a = 0; a < 8; a++)
#pragma unroll
        for (int b2 = 0; b2 < 8; b2++) acc[a][b2] = 0.f;
    for (int e = 0; e < 128; e++) {
        float4 aA = *(const float4*)&kvt[e * WSTR + dg * 8];
        float4 aB = *(const float4*)&kvt[e * WSTR + dg * 8 + 4];
        float4 bA = *(const float4*)&wt [e * WSTR + eg * 8];
        float4 bB = *(const float4*)&wt [e * WSTR + eg * 8 + 4];
        float ad[8] = {aA.x,aA.y,aA.z,aA.w,aB.x,aB.y,aB.z,aB.w};
        float bd[8] = {bA.x,bA.y,bA.z,bA.w,bB.x,bB.y,bB.z,bB.w};
#pragma unroll
        for (int a = 0; a < 8; a++)
#pragma unroll
            for (int b2 = 0; b2 < 8; b2++) acc[a][b2] += ad[a] * bd[b2];
    }
    uint32_t* MhP = g_Mh + bh * 64 * D_;
    uint32_t* MlP = g_Ml + bh * 64 * D_;
#pragma unroll
    for (int a = 0; a < 8; a += 2)
#pragma unroll
        for (int b2 = 0; b2 < 8; b2++) {
            uint32_t hw, lw;
            packpair(acc[a][b2], acc[a + 1][b2], hw, lw);
            int m = (dg * 8 + a) >> 1;
            MhP[m * D_ + eg * 8 + b2] = hw;
            MlP[m * D_ + eg * 8 + b2] = lw;
        }
}

// ---------------- kernel 6: g_lin = (phi_q @ M)/den + b; 2 q-chunks per CTA ----------------
__global__ void __launch_bounds__(256, 2)
k_lin_pre(const float* __restrict__ q, const float* __restrict__ bias)
{
    extern __shared__ float sm[];
    uint32_t* Mh  = (uint32_t*)sm;            // 64*136 (d-pairs x d')
    uint32_t* Ml  = Mh + 64 * RPSTR;
    uint32_t* PHh = Ml + 64 * RPSTR;          // 64*68 (token rows x d-pairs)
    uint32_t* PHl = PHh + 64 * KPSTR;
    float* ksums  = (float*)(PHl + 64 * KPSTR);  // 128
    float* dens   = ksums + 128;                 // 64
    float* bs     = dens + 64;                   // 128

    const uint32_t PHhB = smem_u32(PHh);
    const uint32_t PHlB = PHhB + 64 * KPSTR * 4;

    int bh = blockIdx.x >> 4, cb0 = (blockIdx.x & 15) * 2;
    int tid = threadIdx.x, warp = tid >> 5, lane = tid & 31;
    int g = lane >> 2, t = lane & 3;
    int wm = warp >> 2, wn = warp & 3;

    for (int i = tid; i < 64 * 32; i += 256) {
        int m = i >> 5, dg = i & 31;
        uint4 hv = ((const uint4*)(g_Mh + bh * 64 * D_ + m * D_))[dg];
        uint4 lv = ((const uint4*)(g_Ml + bh * 64 * D_ + m * D_))[dg];
        *(uint4*)&Mh[m * RPSTR + 4 * dg] = hv;
        *(uint4*)&Ml[m * RPSTR + 4 * dg] = lv;
    }
    if (tid < 128) { ksums[tid] = g_ksum[bh * D_ + tid]; bs[tid] = bias[tid]; }

    uint32_t aAddr0 = (lane < 16 ? PHhB : PHlB) + (uint32_t)(wm * 32 + (lane & 15)) * KPSTR * 4;
    uint32_t aAddr1 = aAddr0 + 16 * KPSTR * 4;

    for (int ch2 = 0; ch2 < 2; ch2++) {
        int cb = cb0 + ch2;
        const size_t base = (size_t)bh * L_ * D_ + (size_t)cb * 64 * D_;
        __syncthreads();
        for (int rr = 0; rr < 8; rr++) {
            int row = warp * 8 + rr;
            float4 a = ((const float4*)(q + base + (size_t)row * D_))[lane];
            float m = fmaxf(fmaxf(a.x, a.y), fmaxf(a.z, a.w));
#pragma unroll
            for (int o = 16; o > 0; o >>= 1) m = fmaxf(m, __shfl_xor_sync(0xffffffffu, m, o));
            float ex = __expf(a.x - m), ey = __expf(a.y - m);
            float ez = __expf(a.z - m), ew = __expf(a.w - m);
            float s = ex + ey + ez + ew;
#pragma unroll
            for (int o = 16; o > 0; o >>= 1) s += __shfl_xor_sync(0xffffffffu, s, o);
            float inv = 1.f / s;
            float px = ex * inv, py = ey * inv, pz = ez * inv, pw = ew * inv;
            uint32_t h0, l0, h1, l1;
            packpair(px, py, h0, l0);
            packpair(pz, pw, h1, l1);
            *(uint2*)&PHh[row * KPSTR + 2 * lane] = make_uint2(h0, h1);
            *(uint2*)&PHl[row * KPSTR + 2 * lane] = make_uint2(l0, l1);
            float4 ksv = ((const float4*)ksums)[lane];
            float dp = px*ksv.x + py*ksv.y + pz*ksv.z + pw*ksv.w;
#pragma unroll
            for (int o = 16; o > 0; o >>= 1) dp += __shfl_xor_sync(0xffffffffu, dp, o);
            if (lane == 0) dens[row] = 1e-5f + dp;
        }
        __syncthreads();

        float acc[2][4][4];
#pragma unroll
        for (int mt = 0; mt < 2; mt++)
#pragma unroll
            for (int nt = 0; nt < 4; nt++)
#pragma unroll
                for (int c = 0; c < 4; c++) acc[mt][nt][c] = 0.f;

#pragma unroll
        for (int ks = 0; ks < 16; ks++) {
            int pc = ks * 4 + t;
            uint32_t a[2][4];
            ldsm4(aAddr0 + ks * 16, a[0][0], a[0][1], a[0][2], a[0][3]);
            ldsm4(aAddr1 + ks * 16, a[1][0], a[1][1], a[1][2], a[1][3]);
#pragma unroll
            for (int nt = 0; nt < 4; nt++) {
                int n = wn * 32 + nt * 8 + g;
                uint32_t bhw = Mh[pc * RPSTR + n];
                uint32_t blw = Ml[pc * RPSTR + n];
#pragma unroll
                for (int mt = 0; mt < 2; mt++) {
                    mma16(acc[mt][nt], a[mt][0], a[mt][1], a[mt][2], a[mt][3], bhw, blw);
                    mma16(acc[mt][nt], a[mt][0], a[mt][1], a[mt][2], a[mt][3], blw, bhw);
                }
            }
        }

        float* lp = g_lin + base;
#pragma unroll
        for (int mt = 0; mt < 2; mt++)
#pragma unroll
            for (int nt = 0; nt < 4; nt++) {
                int r  = wm * 32 + mt * 16 + g;
                int cc = wn * 32 + nt * 8 + 2 * t;
                float inv0 = 1.f / dens[r];
                float inv1 = 1.f / dens[r + 8];
                float b0 = bs[cc], b1 = bs[cc + 1];
                *(float2*)&lp[r * D_ + cc] =
                    make_float2(acc[mt][nt][0] * inv0 + b0, acc[mt][nt][1] * inv0 + b1);
                *(float2*)&lp[(r + 8) * D_ + cc] =
                    make_float2(acc[mt][nt][2] * inv1 + b0, acc[mt][nt][3] * inv1 + b1);
            }
    }
}

// ---------------- side stream + events (created once at static init) ----------------
struct StreamInit {
    cudaStream_t s1 = nullptr;
    cudaEvent_t  evFork = nullptr, evJoin = nullptr;
    bool ok = false;
    StreamInit() {
        int lo = 0, hi = 0;
        cudaDeviceGetStreamPriorityRange(&lo, &hi);
        if (cudaStreamCreateWithPriority(&s1, cudaStreamNonBlocking, hi) != cudaSuccess) return;
        if (cudaEventCreateWithFlags(&evFork, cudaEventDisableTiming) != cudaSuccess) return;
        if (cudaEventCreateWithFlags(&evJoin, cudaEventDisableTiming) != cudaSuccess) return;
        ok = true;
    }
};
static StreamInit g_si;

// ---------------- launch ----------------
extern "C" void kernel_launch(void* const* d_in, const int* in_sizes, int n_in,
                              void* d_out, int out_size)
{
    const float* q  = (const float*)d_in[0];
    const float* k  = (const float*)d_in[1];
    const float* v  = (const float*)d_in[2];
    const float* w  = (const float*)d_in[3];
    const float* bp = (const float*)d_in[4];
    float* out = (float*)d_out;

    const int sp_smem = (2*64*KPSTR + 2*4352 + 64*PSSTR + 512) * 4;     //  89600
    const int kv_smem = (4 * 32 * RPSTR) * 4;                           //  69632
    const int m_smem  = (2 * 128 * WSTR) * 4;                           // 135168
    const int lo_smem = (64*RPSTR*2 + 64*KPSTR*2 + 128 + 64 + 128) * 4; // 105728

    cudaFuncSetAttribute(k_sparse,  cudaFuncAttributeMaxDynamicSharedMemorySize, sp_smem);
    cudaFuncSetAttribute(k_kv,      cudaFuncAttributeMaxDynamicSharedMemorySize, kv_smem);
    cudaFuncSetAttribute(k_M,       cudaFuncAttributeMaxDynamicSharedMemorySize, m_smem);
    cudaFuncSetAttribute(k_lin_pre, cudaFuncAttributeMaxDynamicSharedMemorySize, lo_smem);

    void* ksp = nullptr;
    cudaGetSymbolAddress(&ksp, g_ksum);

    if (g_si.ok) {
        // side (high prio): memset -> kv -> red -> M -> lin_pre  (chain A, independent of sparse)
        // main:             bm -> topk, then wait for chain A, then sparse (+g_lin add)
        cudaEventRecord(g_si.evFork, 0);
        cudaStreamWaitEvent(g_si.s1, g_si.evFork, 0);

        cudaMemsetAsync(ksp, 0, sizeof(float) * BH * D_, g_si.s1);
        k_kv<<<BH * NPART, 512, kv_smem, g_si.s1>>>(k, v);
        k_red<<<128, 256, 0, g_si.s1>>>();
        k_M<<<32, 256, m_smem, g_si.s1>>>(w);
        k_lin_pre<<<512, 256, lo_smem, g_si.s1>>>(q, bp);
        cudaEventRecord(g_si.evJoin, g_si.s1);

        k_blockmean<<<2048, 128>>>(q, k);
        k_topk<<<1024, 32>>>();
        cudaStreamWaitEvent(0, g_si.evJoin, 0);
        k_sparse<<<1024, 512, sp_smem>>>(q, k, v, out);
    } else {
        cudaMemsetAsync(ksp, 0, sizeof(float) * BH * D_);
        k_blockmean<<<2048, 128>>>(q, k);
        k_topk<<<1024, 32>>>();
        k_kv<<<BH * NPART, 512, kv_smem>>>(k, v);
        k_red<<<128, 256>>>();
        k_M<<<32, 256, m_smem>>>(w);
        k_lin_pre<<<512, 256, lo_smem>>>(q, bp);
        k_sparse<<<1024, 512, sp_smem>>>(q, k, v, out);
    }
}

// round 16
// speedup vs baseline: 1.0395x; 1.0395x over previous
#include <cuda_runtime.h>
#include <cuda_bf16.h>
#include <math.h>
#include <stdint.h>

// Problem constants: B=2, H=16, L=2048, D=128, BLKQ=BLKK=64, topk=4
#define B_    2
#define H_    16
#define L_    2048
#define D_    128
#define BH    32
#define NBLK  32
#define TOPK  4
#define NPART 4

#define KPSTR 68     // u32 stride, k-pair-packed arrays
#define RPSTR 136    // u32 stride, row-pair-packed arrays
#define PSSTR 68     // u32 stride, per-block packed S (hi [0,32), lo [36,68))
#define WSTR  132    // f32 stride for k_M tiles

// ---------------- static device scratch ----------------
__device__ float g_qb[BH*NBLK*D_];
__device__ float g_kb[BH*NBLK*D_];
__device__ int   g_lut[BH*NBLK*TOPK];
__device__ float g_kvpart[(size_t)BH*NPART*D_*D_];
__device__ float g_kvsum[BH*D_*D_];
__device__ float g_ksum [BH*D_];
__device__ uint32_t g_Mh[BH*64*D_];   // M packed: bf16 hi plane (d-pair rows)
__device__ uint32_t g_Ml[BH*64*D_];   // M packed: bf16 lo plane
__device__ float g_lin[(size_t)BH*L_*D_];   // linear-branch output (incl. bias)

// ---------------- helpers ----------------
__device__ __forceinline__ void mma16(float c[4],
                                      uint32_t a0, uint32_t a1, uint32_t a2, uint32_t a3,
                                      uint32_t b0, uint32_t b1)
{
    asm volatile(
        "mma.sync.aligned.m16n8k16.row.col.f32.bf16.bf16.f32 "
        "{%0,%1,%2,%3},{%4,%5,%6,%7},{%8,%9},{%0,%1,%2,%3};\n"
        : "+f"(c[0]), "+f"(c[1]), "+f"(c[2]), "+f"(c[3])
        : "r"(a0), "r"(a1), "r"(a2), "r"(a3), "r"(b0), "r"(b1));
}

__device__ __forceinline__ void ldsm4(uint32_t addr,
                                      uint32_t& r0, uint32_t& r1, uint32_t& r2, uint32_t& r3)
{
    asm volatile("ldmatrix.sync.aligned.m8n8.x4.shared.b16 {%0,%1,%2,%3}, [%4];"
                 : "=r"(r0), "=r"(r1), "=r"(r2), "=r"(r3) : "r"(addr));
}

__device__ __forceinline__ uint32_t smem_u32(const void* p)
{
    uint32_t a;
    asm("{ .reg .u64 t; cvta.to.shared.u64 t, %1; cvt.u32.u64 %0, t; }" : "=r"(a) : "l"(p));
    return a;
}

// pack (x0, x1) -> hw = bf16(x1)<<16 | bf16(x0), lw = residuals
__device__ __forceinline__ void packpair(float x0, float x1, uint32_t& hw, uint32_t& lw)
{
    uint32_t h;
    asm("cvt.rn.bf16x2.f32 %0, %1, %2;" : "=r"(h) : "f"(x1), "f"(x0));
    float h0 = __uint_as_float(h << 16);
    float h1 = __uint_as_float(h & 0xFFFF0000u);
    uint32_t l;
    asm("cvt.rn.bf16x2.f32 %0, %1, %2;" : "=r"(l) : "f"(x1 - h1), "f"(x0 - h0));
    hw = h; lw = l;
}

__device__ __forceinline__ float bfhi(uint32_t w) { return __uint_as_float(w & 0xFFFF0000u); }
__device__ __forceinline__ float bflo(uint32_t w) { return __uint_as_float(w << 16); }

// ---------------- kernel 1: block means ----------------
__global__ void k_blockmean(const float* __restrict__ q, const float* __restrict__ k)
{
    int id    = blockIdx.x;
    int which = id >> 10;
    int rem   = id & 1023;
    const float* src = which ? k : q;
    float*       dst = which ? g_kb : g_qb;
    int d = threadIdx.x;
    const float* base = src + (size_t)rem * 64 * D_ + d;
    float s = 0.f;
#pragma unroll 8
    for (int r = 0; r < 64; r++) s += base[r * D_];
    dst[rem * D_ + d] = s * (1.0f / 64.0f);
}

// ---------------- kernel 2: top-4 selection ----------------
__global__ void k_topk()
{
    int id   = blockIdx.x;
    int bh   = id >> 5;
    int lane = threadIdx.x;
    const float4* q4 = (const float4*)(g_qb + id * D_);
    const float4* k4 = (const float4*)(g_kb + (bh * NBLK + lane) * D_);
    float s = 0.f;
#pragma unroll
    for (int d4 = 0; d4 < 32; d4++) {
        float4 a = q4[d4], b = k4[d4];
        s += a.x*b.x + a.y*b.y + a.z*b.z + a.w*b.w;
    }
    float val = s;
    for (int t = 0; t < TOPK; t++) {
        float m = val; int mi = lane;
#pragma unroll
        for (int o = 16; o > 0; o >>= 1) {
            float ov = __shfl_xor_sync(0xffffffffu, m,  o);
            int   oi = __shfl_xor_sync(0xffffffffu, mi, o);
            if (ov > m || (ov == m && oi < mi)) { m = ov; mi = oi; }
        }
        if (lane == 0)  g_lut[id * TOPK + t] = mi;
        if (lane == mi) val = -3.0e38f;
    }
}

// ---------------- kernel 3: sparse attention, streaming softmax, 2 CTAs/SM ----------------
__global__ void __launch_bounds__(512, 2)
k_sparse(const float* __restrict__ q, const float* __restrict__ k,
         const float* __restrict__ v, float* __restrict__ out)
{
    extern __shared__ float sm[];
    uint32_t* Qh  = (uint32_t*)sm;        // 64*68
    uint32_t* Ql  = Qh + 64 * KPSTR;
    uint32_t* KVh = Ql + 64 * KPSTR;      // K: 64*68 = 4352 / V: 32*136 = 4352 u32
    uint32_t* KVl = KVh + 4352;
    uint32_t* Su  = KVl + 4352;           // packed S per block: 64 x 68
    float*    red = (float*)(Su + 64 * PSSTR);   // 512 floats rowsum reduce

    const uint32_t QhB  = smem_u32(Qh);
    const uint32_t QlB  = QhB + 64 * KPSTR * 4;
    const uint32_t KVhB = QlB + 64 * KPSTR * 4;
    const uint32_t KVlB = KVhB + 4352 * 4;
    const uint32_t SuB  = KVlB + 4352 * 4;

    int id = blockIdx.x;                  // bh*32 + qb
    int bh = id >> 5, qb = id & 31;
    int tid  = threadIdx.x;
    int warp = tid >> 5, lane = tid & 31;
    int g = lane >> 2, t = lane & 3;
    int wm = warp >> 2, wn = warp & 3;    // 4x4 warps
    const size_t bh_off = (size_t)bh * L_ * D_;
    const float scale = 0.088388347648318447f;   // 1/sqrt(128)

    // stage Q (scaled, packed k-pairs): 64 rows
    for (int i = tid; i < 64 * 32; i += 512) {
        int row = i >> 5, c4 = i & 31;
        float4 val = ((const float4*)(q + bh_off + (size_t)(qb * 64 + row) * D_))[c4];
        uint32_t h0, l0, h1, l1;
        packpair(val.x * scale, val.y * scale, h0, l0);
        packpair(val.z * scale, val.w * scale, h1, l1);
        *(uint2*)&Qh[row * KPSTR + 2 * c4] = make_uint2(h0, h1);
        *(uint2*)&Ql[row * KPSTR + 2 * c4] = make_uint2(l0, l1);
    }

    int blks[4];
#pragma unroll
    for (int tt = 0; tt < 4; tt++) blks[tt] = g_lut[id * TOPK + tt];

    // LDSM lane addresses
    const int r0 = wm * 16;
    uint32_t aAddrQ = (lane < 16 ? QhB : QlB) + (uint32_t)(r0 + (lane & 15)) * KPSTR * 4;
    const int rowB = wn * 16 + ((lane >> 4) << 3) + (lane & 7);
    uint32_t bArr  = (((lane >> 3) & 1) ? KVlB : KVhB);
    uint32_t bAddr = bArr + (uint32_t)rowB * KPSTR * 4;
    uint32_t aAddrS = SuB + ((uint32_t)(r0 + (lane & 15)) * PSSTR + (lane >= 16 ? 36u : 0u)) * 4;

    float o[4][4];
#pragma unroll
    for (int nt = 0; nt < 4; nt++)
#pragma unroll
        for (int c = 0; c < 4; c++) o[nt][c] = 0.f;
    float rs0 = 0.f, rs1 = 0.f;

    for (int pass = 0; pass < 4; pass++) {
        int blk = blks[pass];
        __syncthreads();
        for (int i = tid; i < 64 * 32; i += 512) {
            int row = i >> 5, c4 = i & 31;
            int gr  = blk * 64 + row;
            float4 val = ((const float4*)(k + bh_off + (size_t)gr * D_))[c4];
            uint32_t h0, l0, h1, l1;
            packpair(val.x, val.y, h0, l0);
            packpair(val.z, val.w, h1, l1);
            *(uint2*)&KVh[row * KPSTR + 2 * c4] = make_uint2(h0, h1);
            *(uint2*)&KVl[row * KPSTR + 2 * c4] = make_uint2(l0, l1);
        }
        __syncthreads();

        float acc[2][4];
#pragma unroll
        for (int nt = 0; nt < 2; nt++)
#pragma unroll
            for (int c = 0; c < 4; c++) acc[nt][c] = 0.f;
#pragma unroll
        for (int ks = 0; ks < 16; ks++) {
            uint32_t a0, a1, a2, a3;
            ldsm4(aAddrQ + ks * 16, a0, a1, a2, a3);
            uint32_t b0h, b0l, b1h, b1l;
            ldsm4(bAddr + ks * 16, b0h, b0l, b1h, b1l);
            mma16(acc[0], a0, a1, a2, a3, b0h, b0l);
            mma16(acc[0], a0, a1, a2, a3, b0l, b0h);
            mma16(acc[1], a0, a1, a2, a3, b1h, b1l);
            mma16(acc[1], a0, a1, a2, a3, b1l, b1h);
        }

#pragma unroll
        for (int nt = 0; nt < 2; nt++) {
            float e0 = __expf(acc[nt][0]), e1 = __expf(acc[nt][1]);
            float e2 = __expf(acc[nt][2]), e3 = __expf(acc[nt][3]);
            rs0 += e0 + e1;
            rs1 += e2 + e3;
            int pc = wn * 8 + nt * 4 + t;
            uint32_t hw, lw;
            packpair(e0, e1, hw, lw);
            Su[(r0 + g) * PSSTR + pc]      = hw;
            Su[(r0 + g) * PSSTR + 36 + pc] = lw;
            packpair(e2, e3, hw, lw);
            Su[(r0 + g + 8) * PSSTR + pc]      = hw;
            Su[(r0 + g + 8) * PSSTR + 36 + pc] = lw;
        }
        __syncthreads();
        for (int i = tid; i < 32 * 32; i += 512) {
            int m = i >> 5, dg = i & 31;
            int gr0 = blk * 64 + 2 * m;
            const float* vp = v + bh_off + (size_t)gr0 * D_;
            float4 v0 = ((const float4*)vp)[dg];
            float4 v1 = ((const float4*)(vp + D_))[dg];
            uint32_t hw0, lw0, hw1, lw1, hw2, lw2, hw3, lw3;
            packpair(v0.x, v1.x, hw0, lw0);
            packpair(v0.y, v1.y, hw1, lw1);
            packpair(v0.z, v1.z, hw2, lw2);
            packpair(v0.w, v1.w, hw3, lw3);
            *(uint4*)&KVh[m * RPSTR + 4 * dg] = make_uint4(hw0, hw1, hw2, hw3);
            *(uint4*)&KVl[m * RPSTR + 4 * dg] = make_uint4(lw0, lw1, lw2, lw3);
        }
        __syncthreads();
        int n0 = wn * 32 + g;
#pragma unroll
        for (int ks = 0; ks < 8; ks++) {
            int jp = ks * 4 + t;
            uint32_t a0, a1, a2, a3;
            ldsm4(aAddrS + ks * 16, a0, a1, a2, a3);
#pragma unroll
            for (int nt = 0; nt < 4; nt++) {
                int d = n0 + nt * 8;
                uint32_t bhw = KVh[jp * RPSTR + d];
                uint32_t blw = KVl[jp * RPSTR + d];
                mma16(o[nt], a0, a1, a2, a3, bhw, blw);
                mma16(o[nt], a0, a1, a2, a3, blw, bhw);
            }
        }
    }

#pragma unroll
    for (int o2 = 1; o2 <= 2; o2 <<= 1) {
        rs0 += __shfl_xor_sync(0xffffffffu, rs0, o2);
        rs1 += __shfl_xor_sync(0xffffffffu, rs1, o2);
    }
    if (t == 0) {
        red[(r0 + g) * 4 + wn]     = rs0;
        red[(r0 + g + 8) * 4 + wn] = rs1;
    }
    __syncthreads();
    float inv0 = 1.f / (red[(r0+g)*4+0] + red[(r0+g)*4+1]
                      + red[(r0+g)*4+2] + red[(r0+g)*4+3]);
    float inv1 = 1.f / (red[(r0+g+8)*4+0] + red[(r0+g+8)*4+1]
                      + red[(r0+g+8)*4+2] + red[(r0+g+8)*4+3]);
    float* op = out + bh_off + (size_t)(qb * 64) * D_;
    int r = r0 + g;
#pragma unroll
    for (int nt = 0; nt < 4; nt++) {
        int cc = wn * 32 + nt * 8 + 2 * t;
        *(float2*)&op[r * D_ + cc]       = make_float2(o[nt][0] * inv0, o[nt][1] * inv0);
        *(float2*)&op[(r + 8) * D_ + cc] = make_float2(o[nt][2] * inv1, o[nt][3] * inv1);
    }
}

// ---------------- kernel 4: kvsum/ksum partials (bf16-pair mma, 16 warps) ----------------
__global__ void __launch_bounds__(512, 1)
k_kv(const float* __restrict__ k, const float* __restrict__ v)
{
    extern __shared__ float sm[];
    uint32_t* PHh = (uint32_t*)sm;          // 32*136
    uint32_t* PHl = PHh + 32 * RPSTR;
    uint32_t* VVh = PHl + 32 * RPSTR;
    uint32_t* VVl = VVh + 32 * RPSTR;

    int bh   = blockIdx.x >> 2;
    int part = blockIdx.x & 3;
    int tid  = threadIdx.x;
    int warp = tid >> 5, lane = tid & 31;
    int g = lane >> 2, t = lane & 3;
    int wm = warp >> 2, wn = warp & 3;      // tile m32 (d) x n32 (e)
    const size_t bh_off = (size_t)bh * L_ * D_;

    float acc[2][4][4];
#pragma unroll
    for (int mt = 0; mt < 2; mt++)
#pragma unroll
        for (int nt = 0; nt < 4; nt++)
#pragma unroll
            for (int c = 0; c < 4; c++) acc[mt][nt][c] = 0.f;
    float ks_loc = 0.f;

    for (int ch = 0; ch < 8; ch++) {
        int l0 = part * 512 + ch * 64;
        __syncthreads();
#pragma unroll
        for (int pp = 0; pp < 2; pp++) {
            int m = warp * 2 + pp;
            size_t l = bh_off + (size_t)(l0 + 2 * m) * D_;
            float4 k0 = ((const float4*)(k + l))[lane];
            float4 k1 = ((const float4*)(k + l + D_))[lane];
            float mx0 = fmaxf(fmaxf(k0.x, k0.y), fmaxf(k0.z, k0.w));
            float mx1 = fmaxf(fmaxf(k1.x, k1.y), fmaxf(k1.z, k1.w));
#pragma unroll
            for (int o2 = 16; o2 > 0; o2 >>= 1) {
                mx0 = fmaxf(mx0, __shfl_xor_sync(0xffffffffu, mx0, o2));
                mx1 = fmaxf(mx1, __shfl_xor_sync(0xffffffffu, mx1, o2));
            }
            float e0x = __expf(k0.x - mx0), e0y = __expf(k0.y - mx0);
            float e0z = __expf(k0.z - mx0), e0w = __expf(k0.w - mx0);
            float e1x = __expf(k1.x - mx1), e1y = __expf(k1.y - mx1);
            float e1z = __expf(k1.z - mx1), e1w = __expf(k1.w - mx1);
            float s0 = e0x + e0y + e0z + e0w;
            float s1 = e1x + e1y + e1z + e1w;
#pragma unroll
            for (int o2 = 16; o2 > 0; o2 >>= 1) {
                s0 += __shfl_xor_sync(0xffffffffu, s0, o2);
                s1 += __shfl_xor_sync(0xffffffffu, s1, o2);
            }
            float i0 = 1.f / s0, i1 = 1.f / s1;
            uint32_t hw0, lw0, hw1, lw1, hw2, lw2, hw3, lw3;
            packpair(e0x * i0, e1x * i1, hw0, lw0);
            packpair(e0y * i0, e1y * i1, hw1, lw1);
            packpair(e0z * i0, e1z * i1, hw2, lw2);
            packpair(e0w * i0, e1w * i1, hw3, lw3);
            *(uint4*)&PHh[m * RPSTR + 4 * lane] = make_uint4(hw0, hw1, hw2, hw3);
            *(uint4*)&PHl[m * RPSTR + 4 * lane] = make_uint4(lw0, lw1, lw2, lw3);
            float4 v0 = ((const float4*)(v + l))[lane];
            float4 v1 = ((const float4*)(v + l + D_))[lane];
            packpair(v0.x, v1.x, hw0, lw0);
            packpair(v0.y, v1.y, hw1, lw1);
            packpair(v0.z, v1.z, hw2, lw2);
            packpair(v0.w, v1.w, hw3, lw3);
            *(uint4*)&VVh[m * RPSTR + 4 * lane] = make_uint4(hw0, hw1, hw2, hw3);
            *(uint4*)&VVl[m * RPSTR + 4 * lane] = make_uint4(lw0, lw1, lw2, lw3);
        }
        __syncthreads();
        if (tid < 128) {
            float s = 0.f;
#pragma unroll 8
            for (int m = 0; m < 32; m++) {
                uint32_t whi = PHh[m * RPSTR + tid];
                uint32_t wlo = PHl[m * RPSTR + tid];
                s += bfhi(whi) + bflo(whi) + bfhi(wlo) + bflo(wlo);
            }
            ks_loc += s;
        }
#pragma unroll
        for (int ks2 = 0; ks2 < 8; ks2++) {
            int lp = ks2 * 4 + t;
            uint32_t a[2][4];
#pragma unroll
            for (int mt = 0; mt < 2; mt++) {
                int r = wm * 32 + mt * 16 + g;
                a[mt][0] = PHh[lp * RPSTR + r];
                a[mt][1] = PHh[lp * RPSTR + r + 8];
                a[mt][2] = PHl[lp * RPSTR + r];
                a[mt][3] = PHl[lp * RPSTR + r + 8];
            }
#pragma unroll
            for (int nt = 0; nt < 4; nt++) {
                int n = wn * 32 + nt * 8 + g;
                uint32_t bhw = VVh[lp * RPSTR + n];
                uint32_t blw = VVl[lp * RPSTR + n];
#pragma unroll
                for (int mt = 0; mt < 2; mt++) {
                    mma16(acc[mt][nt], a[mt][0], a[mt][1], a[mt][2], a[mt][3], bhw, blw);
                    mma16(acc[mt][nt], a[mt][0], a[mt][1], a[mt][2], a[mt][3], blw, bhw);
                }
            }
        }
    }
    float* dst = g_kvpart + ((size_t)bh * NPART + part) * D_ * D_;
#pragma unroll
    for (int mt = 0; mt < 2; mt++)
#pragma unroll
        for (int nt = 0; nt < 4; nt++) {
            int d0 = wm * 32 + mt * 16 + g;
            int e0 = wn * 32 + nt * 8 + 2 * t;
            *(float2*)&dst[d0 * D_ + e0]       = make_float2(acc[mt][nt][0], acc[mt][nt][1]);
            *(float2*)&dst[(d0 + 8) * D_ + e0] = make_float2(acc[mt][nt][2], acc[mt][nt][3]);
        }
    if (tid < 128) atomicAdd(&g_ksum[bh * D_ + tid], ks_loc);
}

// ---------------- kernel 4b: reduce kv partials ----------------
__global__ void __launch_bounds__(256)
k_red()
{
    int bh = blockIdx.x >> 2, qr = blockIdx.x & 3;
    int tid = threadIdx.x;
#pragma unroll
    for (int j = 0; j < 4; j++) {
        int o = qr * 4096 + j * 1024 + tid * 4;
        float4 s = make_float4(0.f, 0.f, 0.f, 0.f);
#pragma unroll
        for (int p = 0; p < NPART; p++) {
            float4 w = *(const float4*)&g_kvpart[((size_t)bh * NPART + p) * D_ * D_ + o];
            s.x += w.x; s.y += w.y; s.z += w.z; s.w += w.w;
        }
        *(float4*)&g_kvsum[bh * D_ * D_ + o] = s;
    }
}

// ---------------- kernel 5: M = kvsum @ w_proj^T, emitted pre-packed ----------------
__global__ void __launch_bounds__(256)
k_M(const float* __restrict__ w)
{
    extern __shared__ float sm[];
    float* kvt = sm;
    float* wt  = sm + 128 * WSTR;
    int bh = blockIdx.x;
    int tid = threadIdx.x;
    const float* kv = g_kvsum + bh * D_ * D_;
    for (int idx = tid; idx < D_ * D_; idx += 256) {
        int d = idx >> 7, e = idx & 127;
        kvt[e * WSTR + d] = kv[idx];
        wt [e * WSTR + d] = w[idx];
    }
    __syncthreads();
    int dg = tid >> 4, eg = tid & 15;
    float acc[8][8];
#pragma unroll
    for (int a = 0; a < 8; a++)
#pragma unroll
        for (int b2 = 0; b2 < 8; b2++) acc[a][b2] = 0.f;
    for (int e = 0; e < 128; e++) {
        float4 aA = *(const float4*)&kvt[e * WSTR + dg * 8];
        float4 aB = *(const float4*)&kvt[e * WSTR + dg * 8 + 4];
        float4 bA = *(const float4*)&wt [e * WSTR + eg * 8];
        float4 bB = *(const float4*)&wt [e * WSTR + eg * 8 + 4];
        float ad[8] = {aA.x,aA.y,aA.z,aA.w,aB.x,aB.y,aB.z,aB.w};
        float bd[8] = {bA.x,bA.y,bA.z,bA.w,bB.x,bB.y,bB.z,bB.w};
#pragma unroll
        for (int a = 0; a < 8; a++)
#pragma unroll
            for (int b2 = 0; b2 < 8; b2++) acc[a][b2] += ad[a] * bd[b2];
    }
    uint32_t* MhP = g_Mh + bh * 64 * D_;
    uint32_t* MlP = g_Ml + bh * 64 * D_;
#pragma unroll
    for (int a = 0; a < 8; a += 2)
#pragma unroll
        for (int b2 = 0; b2 < 8; b2++) {
            uint32_t hw, lw;
            packpair(acc[a][b2], acc[a + 1][b2], hw, lw);
            int m = (dg * 8 + a) >> 1;
            MhP[m * D_ + eg * 8 + b2] = hw;
            MlP[m * D_ + eg * 8 + b2] = lw;
        }
}

// ---------------- kernel 6: g_lin = (phi_q @ M)/den + b; 2 q-chunks per CTA ----------------
__global__ void __launch_bounds__(256, 2)
k_lin_pre(const float* __restrict__ q, const float* __restrict__ bias)
{
    extern __shared__ float sm[];
    uint32_t* Mh  = (uint32_t*)sm;            // 64*136 (d-pairs x d')
    uint32_t* Ml  = Mh + 64 * RPSTR;
    uint32_t* PHh = Ml + 64 * RPSTR;          // 64*68 (token rows x d-pairs)
    uint32_t* PHl = PHh + 64 * KPSTR;
    float* ksums  = (float*)(PHl + 64 * KPSTR);  // 128
    float* dens   = ksums + 128;                 // 64
    float* bs     = dens + 64;                   // 128

    const uint32_t PHhB = smem_u32(PHh);
    const uint32_t PHlB = PHhB + 64 * KPSTR * 4;

    int bh = blockIdx.x >> 4, cb0 = (blockIdx.x & 15) * 2;
    int tid = threadIdx.x, warp = tid >> 5, lane = tid & 31;
    int g = lane >> 2, t = lane & 3;
    int wm = warp >> 2, wn = warp & 3;

    for (int i = tid; i < 64 * 32; i += 256) {
        int m = i >> 5, dg = i & 31;
        uint4 hv = ((const uint4*)(g_Mh + bh * 64 * D_ + m * D_))[dg];
        uint4 lv = ((const uint4*)(g_Ml + bh * 64 * D_ + m * D_))[dg];
        *(uint4*)&Mh[m * RPSTR + 4 * dg] = hv;
        *(uint4*)&Ml[m * RPSTR + 4 * dg] = lv;
    }
    if (tid < 128) { ksums[tid] = g_ksum[bh * D_ + tid]; bs[tid] = bias[tid]; }

    uint32_t aAddr0 = (lane < 16 ? PHhB : PHlB) + (uint32_t)(wm * 32 + (lane & 15)) * KPSTR * 4;
    uint32_t aAddr1 = aAddr0 + 16 * KPSTR * 4;

    for (int ch2 = 0; ch2 < 2; ch2++) {
        int cb = cb0 + ch2;
        const size_t base = (size_t)bh * L_ * D_ + (size_t)cb * 64 * D_;
        __syncthreads();
        for (int rr = 0; rr < 8; rr++) {
            int row = warp * 8 + rr;
            float4 a = ((const float4*)(q + base + (size_t)row * D_))[lane];
            float m = fmaxf(fmaxf(a.x, a.y), fmaxf(a.z, a.w));
#pragma unroll
            for (int o = 16; o > 0; o >>= 1) m = fmaxf(m, __shfl_xor_sync(0xffffffffu, m, o));
            float ex = __expf(a.x - m), ey = __expf(a.y - m);
            float ez = __expf(a.z - m), ew = __expf(a.w - m);
            float s = ex + ey + ez + ew;
#pragma unroll
            for (int o = 16; o > 0; o >>= 1) s += __shfl_xor_sync(0xffffffffu, s, o);
            float inv = 1.f / s;
            float px = ex * inv, py = ey * inv, pz = ez * inv, pw = ew * inv;
            uint32_t h0, l0, h1, l1;
            packpair(px, py, h0, l0);
            packpair(pz, pw, h1, l1);
            *(uint2*)&PHh[row * KPSTR + 2 * lane] = make_uint2(h0, h1);
            *(uint2*)&PHl[row * KPSTR + 2 * lane] = make_uint2(l0, l1);
            float4 ksv = ((const float4*)ksums)[lane];
            float dp = px*ksv.x + py*ksv.y + pz*ksv.z + pw*ksv.w;
#pragma unroll
            for (int o = 16; o > 0; o >>= 1) dp += __shfl_xor_sync(0xffffffffu, dp, o);
            if (lane == 0) dens[row] = 1e-5f + dp;
        }
        __syncthreads();

        float acc[2][4][4];
#pragma unroll
        for (int mt = 0; mt < 2; mt++)
#pragma unroll
            for (int nt = 0; nt < 4; nt++)
#pragma unroll
                for (int c = 0; c < 4; c++) acc[mt][nt][c] = 0.f;

#pragma unroll
        for (int ks = 0; ks < 16; ks++) {
            int pc = ks * 4 + t;
            uint32_t a[2][4];
            ldsm4(aAddr0 + ks * 16, a[0][0], a[0][1], a[0][2], a[0][3]);
            ldsm4(aAddr1 + ks * 16, a[1][0], a[1][1], a[1][2], a[1][3]);
#pragma unroll
            for (int nt = 0; nt < 4; nt++) {
                int n = wn * 32 + nt * 8 + g;
                uint32_t bhw = Mh[pc * RPSTR + n];
                uint32_t blw = Ml[pc * RPSTR + n];
#pragma unroll
                for (int mt = 0; mt < 2; mt++) {
                    mma16(acc[mt][nt], a[mt][0], a[mt][1], a[mt][2], a[mt][3], bhw, blw);
                    mma16(acc[mt][nt], a[mt][0], a[mt][1], a[mt][2], a[mt][3], blw, bhw);
                }
            }
        }

        float* lp = g_lin + base;
#pragma unroll
        for (int mt = 0; mt < 2; mt++)
#pragma unroll
            for (int nt = 0; nt < 4; nt++) {
                int r  = wm * 32 + mt * 16 + g;
                int cc = wn * 32 + nt * 8 + 2 * t;
                float inv0 = 1.f / dens[r];
                float inv1 = 1.f / dens[r + 8];
                float b0 = bs[cc], b1 = bs[cc + 1];
                *(float2*)&lp[r * D_ + cc] =
                    make_float2(acc[mt][nt][0] * inv0 + b0, acc[mt][nt][1] * inv0 + b1);
                *(float2*)&lp[(r + 8) * D_ + cc] =
                    make_float2(acc[mt][nt][2] * inv1 + b0, acc[mt][nt][3] * inv1 + b1);
            }
    }
}

// ---------------- kernel 7: out += g_lin (pure bandwidth) ----------------
__global__ void __launch_bounds__(256)
k_add(float* __restrict__ out)
{
    size_t i = ((size_t)blockIdx.x * 256 + threadIdx.x) * 4;
    float4 a = *(const float4*)&out[i];
    float4 b = *(const float4*)&g_lin[i];
    a.x += b.x; a.y += b.y; a.z += b.z; a.w += b.w;
    *(float4*)&out[i] = a;
}

// ---------------- side stream + events (created once at static init) ----------------
struct StreamInit {
    cudaStream_t s1 = nullptr;
    cudaEvent_t  evFork = nullptr, evJoin = nullptr;
    bool ok = false;
    StreamInit() {
        int lo = 0, hi = 0;
        cudaDeviceGetStreamPriorityRange(&lo, &hi);   // lo = lowest priority
        if (cudaStreamCreateWithPriority(&s1, cudaStreamNonBlocking, lo) != cudaSuccess) return;
        if (cudaEventCreateWithFlags(&evFork, cudaEventDisableTiming) != cudaSuccess) return;
        if (cudaEventCreateWithFlags(&evJoin, cudaEventDisableTiming) != cudaSuccess) return;
        ok = true;
    }
};
static StreamInit g_si;

// ---------------- launch ----------------
extern "C" void kernel_launch(void* const* d_in, const int* in_sizes, int n_in,
                              void* d_out, int out_size)
{
    const float* q  = (const float*)d_in[0];
    const float* k  = (const float*)d_in[1];
    const float* v  = (const float*)d_in[2];
    const float* w  = (const float*)d_in[3];
    const float* bp = (const float*)d_in[4];
    float* out = (float*)d_out;

    const int sp_smem = (2*64*KPSTR + 2*4352 + 64*PSSTR + 512) * 4;     //  89600
    const int kv_smem = (4 * 32 * RPSTR) * 4;                           //  69632
    const int m_smem  = (2 * 128 * WSTR) * 4;                           // 135168
    const int lo_smem = (64*RPSTR*2 + 64*KPSTR*2 + 128 + 64 + 128) * 4; // 105728

    cudaFuncSetAttribute(k_sparse,  cudaFuncAttributeMaxDynamicSharedMemorySize, sp_smem);
    cudaFuncSetAttribute(k_kv,      cudaFuncAttributeMaxDynamicSharedMemorySize, kv_smem);
    cudaFuncSetAttribute(k_M,       cudaFuncAttributeMaxDynamicSharedMemorySize, m_smem);
    cudaFuncSetAttribute(k_lin_pre, cudaFuncAttributeMaxDynamicSharedMemorySize, lo_smem);

    void* ksp = nullptr;
    cudaGetSymbolAddress(&ksp, g_ksum);

    if (g_si.ok) {
        // side (low prio): memset -> kv -> red -> M -> lin_pre   (concurrent with sparse)
        // main:            bm -> topk -> sparse (o_s only); join; k_add (out += g_lin)
        cudaEventRecord(g_si.evFork, 0);
        cudaStreamWaitEvent(g_si.s1, g_si.evFork, 0);

        k_blockmean<<<2048, 128>>>(q, k);
        k_topk<<<1024, 32>>>();
        k_sparse<<<1024, 512, sp_smem>>>(q, k, v, out);

        cudaMemsetAsync(ksp, 0, sizeof(float) * BH * D_, g_si.s1);
        k_kv<<<BH * NPART, 512, kv_smem, g_si.s1>>>(k, v);
        k_red<<<128, 256, 0, g_si.s1>>>();
        k_M<<<32, 256, m_smem, g_si.s1>>>(w);
        k_lin_pre<<<512, 256, lo_smem, g_si.s1>>>(q, bp);
        cudaEventRecord(g_si.evJoin, g_si.s1);

        cudaStreamWaitEvent(0, g_si.evJoin, 0);
        k_add<<<(BH * L_ * D_) / (256 * 4), 256>>>(out);
    } else {
        cudaMemsetAsync(ksp, 0, sizeof(float) * BH * D_);
        k_blockmean<<<2048, 128>>>(q, k);
        k_topk<<<1024, 32>>>();
        k_kv<<<BH * NPART, 512, kv_smem>>>(k, v);
        k_sparse<<<1024, 512, sp_smem>>>(q, k, v, out);
        k_red<<<128, 256>>>();
        k_M<<<32, 256, m_smem>>>(w);
        k_lin_pre<<<512, 256, lo_smem>>>(q, bp);
        k_add<<<(BH * L_ * D_) / (256 * 4), 256>>>(out);
    }
}

// round 17
// speedup vs baseline: 1.1569x; 1.1130x over previous
#include <cuda_runtime.h>
#include <cuda_bf16.h>
#include <math.h>
#include <stdint.h>

// Problem constants: B=2, H=16, L=2048, D=128, BLKQ=BLKK=64, topk=4
#define B_    2
#define H_    16
#define L_    2048
#define D_    128
#define BH    32
#define NBLK  32
#define TOPK  4
#define NPART 4

#define KPSTR 68     // u32 stride, k-pair-packed arrays
#define RPSTR 136    // u32 stride, row-pair-packed arrays
#define PSSTR 68     // u32 stride, per-block packed S (hi [0,32), lo [36,68))
#define WSTR  132    // f32 stride for k_M tiles

// ---------------- static device scratch ----------------
__device__ float g_qb[BH*NBLK*D_];
__device__ float g_kb[BH*NBLK*D_];
__device__ int   g_lut[BH*NBLK*TOPK];
__device__ float g_kvpart[(size_t)BH*NPART*D_*D_];
__device__ float g_kvsum[BH*D_*D_];
__device__ float g_ksum [BH*D_];
__device__ uint32_t g_Mh[BH*64*D_];   // M packed: bf16 hi plane (d-pair rows)
__device__ uint32_t g_Ml[BH*64*D_];   // M packed: bf16 lo plane

// ---------------- helpers ----------------
__device__ __forceinline__ void mma16(float c[4],
                                      uint32_t a0, uint32_t a1, uint32_t a2, uint32_t a3,
                                      uint32_t b0, uint32_t b1)
{
    asm volatile(
        "mma.sync.aligned.m16n8k16.row.col.f32.bf16.bf16.f32 "
        "{%0,%1,%2,%3},{%4,%5,%6,%7},{%8,%9},{%0,%1,%2,%3};\n"
        : "+f"(c[0]), "+f"(c[1]), "+f"(c[2]), "+f"(c[3])
        : "r"(a0), "r"(a1), "r"(a2), "r"(a3), "r"(b0), "r"(b1));
}

__device__ __forceinline__ void ldsm4(uint32_t addr,
                                      uint32_t& r0, uint32_t& r1, uint32_t& r2, uint32_t& r3)
{
    asm volatile("ldmatrix.sync.aligned.m8n8.x4.shared.b16 {%0,%1,%2,%3}, [%4];"
                 : "=r"(r0), "=r"(r1), "=r"(r2), "=r"(r3) : "r"(addr));
}

__device__ __forceinline__ uint32_t smem_u32(const void* p)
{
    uint32_t a;
    asm("{ .reg .u64 t; cvta.to.shared.u64 t, %1; cvt.u32.u64 %0, t; }" : "=r"(a) : "l"(p));
    return a;
}

// pack (x0, x1) -> hw = bf16(x1)<<16 | bf16(x0), lw = residuals
__device__ __forceinline__ void packpair(float x0, float x1, uint32_t& hw, uint32_t& lw)
{
    uint32_t h;
    asm("cvt.rn.bf16x2.f32 %0, %1, %2;" : "=r"(h) : "f"(x1), "f"(x0));
    float h0 = __uint_as_float(h << 16);
    float h1 = __uint_as_float(h & 0xFFFF0000u);
    uint32_t l;
    asm("cvt.rn.bf16x2.f32 %0, %1, %2;" : "=r"(l) : "f"(x1 - h1), "f"(x0 - h0));
    hw = h; lw = l;
}

__device__ __forceinline__ float bfhi(uint32_t w) { return __uint_as_float(w & 0xFFFF0000u); }
__device__ __forceinline__ float bflo(uint32_t w) { return __uint_as_float(w << 16); }

// ---------------- kernel 1: block means ----------------
__global__ void k_blockmean(const float* __restrict__ q, const float* __restrict__ k)
{
    int id    = blockIdx.x;
    int which = id >> 10;
    int rem   = id & 1023;
    const float* src = which ? k : q;
    float*       dst = which ? g_kb : g_qb;
    int d = threadIdx.x;
    const float* base = src + (size_t)rem * 64 * D_ + d;
    float s = 0.f;
#pragma unroll 8
    for (int r = 0; r < 64; r++) s += base[r * D_];
    dst[rem * D_ + d] = s * (1.0f / 64.0f);
}

// ---------------- kernel 2: top-4 selection ----------------
__global__ void k_topk()
{
    int id   = blockIdx.x;
    int bh   = id >> 5;
    int lane = threadIdx.x;
    const float4* q4 = (const float4*)(g_qb + id * D_);
    const float4* k4 = (const float4*)(g_kb + (bh * NBLK + lane) * D_);
    float s = 0.f;
#pragma unroll
    for (int d4 = 0; d4 < 32; d4++) {
        float4 a = q4[d4], b = k4[d4];
        s += a.x*b.x + a.y*b.y + a.z*b.z + a.w*b.w;
    }
    float val = s;
    for (int t = 0; t < TOPK; t++) {
        float m = val; int mi = lane;
#pragma unroll
        for (int o = 16; o > 0; o >>= 1) {
            float ov = __shfl_xor_sync(0xffffffffu, m,  o);
            int   oi = __shfl_xor_sync(0xffffffffu, mi, o);
            if (ov > m || (ov == m && oi < mi)) { m = ov; mi = oi; }
        }
        if (lane == 0)  g_lut[id * TOPK + t] = mi;
        if (lane == mi) val = -3.0e38f;
    }
}

// ---------------- kernel 3: sparse attention, streaming softmax, 2 CTAs/SM ----------------
__global__ void __launch_bounds__(512, 2)
k_sparse(const float* __restrict__ q, const float* __restrict__ k,
         const float* __restrict__ v, float* __restrict__ out)
{
    extern __shared__ float sm[];
    uint32_t* Qh  = (uint32_t*)sm;        // 64*68
    uint32_t* Ql  = Qh + 64 * KPSTR;
    uint32_t* KVh = Ql + 64 * KPSTR;      // K: 64*68 = 4352 / V: 32*136 = 4352 u32
    uint32_t* KVl = KVh + 4352;
    uint32_t* Su  = KVl + 4352;           // packed S per block: 64 x 68
    float*    red = (float*)(Su + 64 * PSSTR);   // 512 floats rowsum reduce

    const uint32_t QhB  = smem_u32(Qh);
    const uint32_t QlB  = QhB + 64 * KPSTR * 4;
    const uint32_t KVhB = QlB + 64 * KPSTR * 4;
    const uint32_t KVlB = KVhB + 4352 * 4;
    const uint32_t SuB  = KVlB + 4352 * 4;

    int id = blockIdx.x;                  // bh*32 + qb
    int bh = id >> 5, qb = id & 31;
    int tid  = threadIdx.x;
    int warp = tid >> 5, lane = tid & 31;
    int g = lane >> 2, t = lane & 3;
    int wm = warp >> 2, wn = warp & 3;    // 4x4 warps
    const size_t bh_off = (size_t)bh * L_ * D_;
    const float scale = 0.088388347648318447f;   // 1/sqrt(128)

    // stage Q (scaled, packed k-pairs): 64 rows
    for (int i = tid; i < 64 * 32; i += 512) {
        int row = i >> 5, c4 = i & 31;
        float4 val = ((const float4*)(q + bh_off + (size_t)(qb * 64 + row) * D_))[c4];
        uint32_t h0, l0, h1, l1;
        packpair(val.x * scale, val.y * scale, h0, l0);
        packpair(val.z * scale, val.w * scale, h1, l1);
        *(uint2*)&Qh[row * KPSTR + 2 * c4] = make_uint2(h0, h1);
        *(uint2*)&Ql[row * KPSTR + 2 * c4] = make_uint2(l0, l1);
    }

    int blks[4];
#pragma unroll
    for (int tt = 0; tt < 4; tt++) blks[tt] = g_lut[id * TOPK + tt];

    // LDSM lane addresses
    const int r0 = wm * 16;
    uint32_t aAddrQ = (lane < 16 ? QhB : QlB) + (uint32_t)(r0 + (lane & 15)) * KPSTR * 4;
    const int rowB = wn * 16 + ((lane >> 4) << 3) + (lane & 7);
    uint32_t bArr  = (((lane >> 3) & 1) ? KVlB : KVhB);
    uint32_t bAddr = bArr + (uint32_t)rowB * KPSTR * 4;
    uint32_t aAddrS = SuB + ((uint32_t)(r0 + (lane & 15)) * PSSTR + (lane >= 16 ? 36u : 0u)) * 4;

    float o[4][4];
#pragma unroll
    for (int nt = 0; nt < 4; nt++)
#pragma unroll
        for (int c = 0; c < 4; c++) o[nt][c] = 0.f;
    float rs0 = 0.f, rs1 = 0.f;

    for (int pass = 0; pass < 4; pass++) {
        int blk = blks[pass];
        __syncthreads();
        for (int i = tid; i < 64 * 32; i += 512) {
            int row = i >> 5, c4 = i & 31;
            int gr  = blk * 64 + row;
            float4 val = ((const float4*)(k + bh_off + (size_t)gr * D_))[c4];
            uint32_t h0, l0, h1, l1;
            packpair(val.x, val.y, h0, l0);
            packpair(val.z, val.w, h1, l1);
            *(uint2*)&KVh[row * KPSTR + 2 * c4] = make_uint2(h0, h1);
            *(uint2*)&KVl[row * KPSTR + 2 * c4] = make_uint2(l0, l1);
        }
        __syncthreads();

        float acc[2][4];
#pragma unroll
        for (int nt = 0; nt < 2; nt++)
#pragma unroll
            for (int c = 0; c < 4; c++) acc[nt][c] = 0.f;
#pragma unroll
        for (int ks = 0; ks < 16; ks++) {
            uint32_t a0, a1, a2, a3;
            ldsm4(aAddrQ + ks * 16, a0, a1, a2, a3);
            uint32_t b0h, b0l, b1h, b1l;
            ldsm4(bAddr + ks * 16, b0h, b0l, b1h, b1l);
            mma16(acc[0], a0, a1, a2, a3, b0h, b0l);
            mma16(acc[0], a0, a1, a2, a3, b0l, b0h);
            mma16(acc[1], a0, a1, a2, a3, b1h, b1l);
            mma16(acc[1], a0, a1, a2, a3, b1l, b1h);
        }

#pragma unroll
        for (int nt = 0; nt < 2; nt++) {
            float e0 = __expf(acc[nt][0]), e1 = __expf(acc[nt][1]);
            float e2 = __expf(acc[nt][2]), e3 = __expf(acc[nt][3]);
            rs0 += e0 + e1;
            rs1 += e2 + e3;
            int pc = wn * 8 + nt * 4 + t;
            uint32_t hw, lw;
            packpair(e0, e1, hw, lw);
            Su[(r0 + g) * PSSTR + pc]      = hw;
            Su[(r0 + g) * PSSTR + 36 + pc] = lw;
            packpair(e2, e3, hw, lw);
            Su[(r0 + g + 8) * PSSTR + pc]      = hw;
            Su[(r0 + g + 8) * PSSTR + 36 + pc] = lw;
        }
        __syncthreads();
        for (int i = tid; i < 32 * 32; i += 512) {
            int m = i >> 5, dg = i & 31;
            int gr0 = blk * 64 + 2 * m;
            const float* vp = v + bh_off + (size_t)gr0 * D_;
            float4 v0 = ((const float4*)vp)[dg];
            float4 v1 = ((const float4*)(vp + D_))[dg];
            uint32_t hw0, lw0, hw1, lw1, hw2, lw2, hw3, lw3;
            packpair(v0.x, v1.x, hw0, lw0);
            packpair(v0.y, v1.y, hw1, lw1);
            packpair(v0.z, v1.z, hw2, lw2);
            packpair(v0.w, v1.w, hw3, lw3);
            *(uint4*)&KVh[m * RPSTR + 4 * dg] = make_uint4(hw0, hw1, hw2, hw3);
            *(uint4*)&KVl[m * RPSTR + 4 * dg] = make_uint4(lw0, lw1, lw2, lw3);
        }
        __syncthreads();
        int n0 = wn * 32 + g;
#pragma unroll
        for (int ks = 0; ks < 8; ks++) {
            int jp = ks * 4 + t;
            uint32_t a0, a1, a2, a3;
            ldsm4(aAddrS + ks * 16, a0, a1, a2, a3);
#pragma unroll
            for (int nt = 0; nt < 4; nt++) {
                int d = n0 + nt * 8;
                uint32_t bhw = KVh[jp * RPSTR + d];
                uint32_t blw = KVl[jp * RPSTR + d];
                mma16(o[nt], a0, a1, a2, a3, bhw, blw);
                mma16(o[nt], a0, a1, a2, a3, blw, bhw);
            }
        }
    }

#pragma unroll
    for (int o2 = 1; o2 <= 2; o2 <<= 1) {
        rs0 += __shfl_xor_sync(0xffffffffu, rs0, o2);
        rs1 += __shfl_xor_sync(0xffffffffu, rs1, o2);
    }
    if (t == 0) {
        red[(r0 + g) * 4 + wn]     = rs0;
        red[(r0 + g + 8) * 4 + wn] = rs1;
    }
    __syncthreads();
    float inv0 = 1.f / (red[(r0+g)*4+0] + red[(r0+g)*4+1]
                      + red[(r0+g)*4+2] + red[(r0+g)*4+3]);
    float inv1 = 1.f / (red[(r0+g+8)*4+0] + red[(r0+g+8)*4+1]
                      + red[(r0+g+8)*4+2] + red[(r0+g+8)*4+3]);
    float* op = out + bh_off + (size_t)(qb * 64) * D_;
    int r = r0 + g;
#pragma unroll
    for (int nt = 0; nt < 4; nt++) {
        int cc = wn * 32 + nt * 8 + 2 * t;
        *(float2*)&op[r * D_ + cc]       = make_float2(o[nt][0] * inv0, o[nt][1] * inv0);
        *(float2*)&op[(r + 8) * D_ + cc] = make_float2(o[nt][2] * inv1, o[nt][3] * inv1);
    }
}

// ---------------- kernel 4: kvsum/ksum partials (bf16-pair mma, 16 warps) ----------------
__global__ void __launch_bounds__(512, 1)
k_kv(const float* __restrict__ k, const float* __restrict__ v)
{
    extern __shared__ float sm[];
    uint32_t* PHh = (uint32_t*)sm;          // 32*136
    uint32_t* PHl = PHh + 32 * RPSTR;
    uint32_t* VVh = PHl + 32 * RPSTR;
    uint32_t* VVl = VVh + 32 * RPSTR;

    int bh   = blockIdx.x >> 2;
    int part = blockIdx.x & 3;
    int tid  = threadIdx.x;
    int warp = tid >> 5, lane = tid & 31;
    int g = lane >> 2, t = lane & 3;
    int wm = warp >> 2, wn = warp & 3;      // tile m32 (d) x n32 (e)
    const size_t bh_off = (size_t)bh * L_ * D_;

    float acc[2][4][4];
#pragma unroll
    for (int mt = 0; mt < 2; mt++)
#pragma unroll
        for (int nt = 0; nt < 4; nt++)
#pragma unroll
            for (int c = 0; c < 4; c++) acc[mt][nt][c] = 0.f;
    float ks_loc = 0.f;

    for (int ch = 0; ch < 8; ch++) {
        int l0 = part * 512 + ch * 64;
        __syncthreads();
#pragma unroll
        for (int pp = 0; pp < 2; pp++) {
            int m = warp * 2 + pp;
            size_t l = bh_off + (size_t)(l0 + 2 * m) * D_;
            float4 k0 = ((const float4*)(k + l))[lane];
            float4 k1 = ((const float4*)(k + l + D_))[lane];
            float mx0 = fmaxf(fmaxf(k0.x, k0.y), fmaxf(k0.z, k0.w));
            float mx1 = fmaxf(fmaxf(k1.x, k1.y), fmaxf(k1.z, k1.w));
#pragma unroll
            for (int o2 = 16; o2 > 0; o2 >>= 1) {
                mx0 = fmaxf(mx0, __shfl_xor_sync(0xffffffffu, mx0, o2));
                mx1 = fmaxf(mx1, __shfl_xor_sync(0xffffffffu, mx1, o2));
            }
            float e0x = __expf(k0.x - mx0), e0y = __expf(k0.y - mx0);
            float e0z = __expf(k0.z - mx0), e0w = __expf(k0.w - mx0);
            float e1x = __expf(k1.x - mx1), e1y = __expf(k1.y - mx1);
            float e1z = __expf(k1.z - mx1), e1w = __expf(k1.w - mx1);
            float s0 = e0x + e0y + e0z + e0w;
            float s1 = e1x + e1y + e1z + e1w;
#pragma unroll
            for (int o2 = 16; o2 > 0; o2 >>= 1) {
                s0 += __shfl_xor_sync(0xffffffffu, s0, o2);
                s1 += __shfl_xor_sync(0xffffffffu, s1, o2);
            }
            float i0 = 1.f / s0, i1 = 1.f / s1;
            uint32_t hw0, lw0, hw1, lw1, hw2, lw2, hw3, lw3;
            packpair(e0x * i0, e1x * i1, hw0, lw0);
            packpair(e0y * i0, e1y * i1, hw1, lw1);
            packpair(e0z * i0, e1z * i1, hw2, lw2);
            packpair(e0w * i0, e1w * i1, hw3, lw3);
            *(uint4*)&PHh[m * RPSTR + 4 * lane] = make_uint4(hw0, hw1, hw2, hw3);
            *(uint4*)&PHl[m * RPSTR + 4 * lane] = make_uint4(lw0, lw1, lw2, lw3);
            float4 v0 = ((const float4*)(v + l))[lane];
            float4 v1 = ((const float4*)(v + l + D_))[lane];
            packpair(v0.x, v1.x, hw0, lw0);
            packpair(v0.y, v1.y, hw1, lw1);
            packpair(v0.z, v1.z, hw2, lw2);
            packpair(v0.w, v1.w, hw3, lw3);
            *(uint4*)&VVh[m * RPSTR + 4 * lane] = make_uint4(hw0, hw1, hw2, hw3);
            *(uint4*)&VVl[m * RPSTR + 4 * lane] = make_uint4(lw0, lw1, lw2, lw3);
        }
        __syncthreads();
        if (tid < 128) {
            float s = 0.f;
#pragma unroll 8
            for (int m = 0; m < 32; m++) {
                uint32_t whi = PHh[m * RPSTR + tid];
                uint32_t wlo = PHl[m * RPSTR + tid];
                s += bfhi(whi) + bflo(whi) + bfhi(wlo) + bflo(wlo);
            }
            ks_loc += s;
        }
#pragma unroll
        for (int ks2 = 0; ks2 < 8; ks2++) {
            int lp = ks2 * 4 + t;
            uint32_t a[2][4];
#pragma unroll
            for (int mt = 0; mt < 2; mt++) {
                int r = wm * 32 + mt * 16 + g;
                a[mt][0] = PHh[lp * RPSTR + r];
                a[mt][1] = PHh[lp * RPSTR + r + 8];
                a[mt][2] = PHl[lp * RPSTR + r];
                a[mt][3] = PHl[lp * RPSTR + r + 8];
            }
#pragma unroll
            for (int nt = 0; nt < 4; nt++) {
                int n = wn * 32 + nt * 8 + g;
                uint32_t bhw = VVh[lp * RPSTR + n];
                uint32_t blw = VVl[lp * RPSTR + n];
#pragma unroll
                for (int mt = 0; mt < 2; mt++) {
                    mma16(acc[mt][nt], a[mt][0], a[mt][1], a[mt][2], a[mt][3], bhw, blw);
                    mma16(acc[mt][nt], a[mt][0], a[mt][1], a[mt][2], a[mt][3], blw, bhw);
                }
            }
        }
    }
    float* dst = g_kvpart + ((size_t)bh * NPART + part) * D_ * D_;
#pragma unroll
    for (int mt = 0; mt < 2; mt++)
#pragma unroll
        for (int nt = 0; nt < 4; nt++) {
            int d0 = wm * 32 + mt * 16 + g;
            int e0 = wn * 32 + nt * 8 + 2 * t;
            *(float2*)&dst[d0 * D_ + e0]       = make_float2(acc[mt][nt][0], acc[mt][nt][1]);
            *(float2*)&dst[(d0 + 8) * D_ + e0] = make_float2(acc[mt][nt][2], acc[mt][nt][3]);
        }
    if (tid < 128) atomicAdd(&g_ksum[bh * D_ + tid], ks_loc);
}

// ---------------- kernel 4b: reduce kv partials ----------------
__global__ void __launch_bounds__(256)
k_red()
{
    int bh = blockIdx.x >> 2, qr = blockIdx.x & 3;
    int tid = threadIdx.x;
#pragma unroll
    for (int j = 0; j < 4; j++) {
        int o = qr * 4096 + j * 1024 + tid * 4;
        float4 s = make_float4(0.f, 0.f, 0.f, 0.f);
#pragma unroll
        for (int p = 0; p < NPART; p++) {
            float4 w = *(const float4*)&g_kvpart[((size_t)bh * NPART + p) * D_ * D_ + o];
            s.x += w.x; s.y += w.y; s.z += w.z; s.w += w.w;
        }
        *(float4*)&g_kvsum[bh * D_ * D_ + o] = s;
    }
}

// ---------------- kernel 5: M = kvsum @ w_proj^T, emitted pre-packed ----------------
__global__ void __launch_bounds__(256)
k_M(const float* __restrict__ w)
{
    extern __shared__ float sm[];
    float* kvt = sm;
    float* wt  = sm + 128 * WSTR;
    int bh = blockIdx.x;
    int tid = threadIdx.x;
    const float* kv = g_kvsum + bh * D_ * D_;
    for (int idx = tid; idx < D_ * D_; idx += 256) {
        int d = idx >> 7, e = idx & 127;
        kvt[e * WSTR + d] = kv[idx];
        wt [e * WSTR + d] = w[idx];
    }
    __syncthreads();
    int dg = tid >> 4, eg = tid & 15;
    float acc[8][8];
#pragma unroll
    for (int a = 0; a < 8; a++)
#pragma unroll
        for (int b2 = 0; b2 < 8; b2++) acc[a][b2] = 0.f;
    for (int e = 0; e < 128; e++) {
        float4 aA = *(const float4*)&kvt[e * WSTR + dg * 8];
        float4 aB = *(const float4*)&kvt[e * WSTR + dg * 8 + 4];
        float4 bA = *(const float4*)&wt [e * WSTR + eg * 8];
        float4 bB = *(const float4*)&wt [e * WSTR + eg * 8 + 4];
        float ad[8] = {aA.x,aA.y,aA.z,aA.w,aB.x,aB.y,aB.z,aB.w};
        float bd[8] = {bA.x,bA.y,bA.z,bA.w,bB.x,bB.y,bB.z,bB.w};
#pragma unroll
        for (int a = 0; a < 8; a++)
#pragma unroll
            for (int b2 = 0; b2 < 8; b2++) acc[a][b2] += ad[a] * bd[b2];
    }
    uint32_t* MhP = g_Mh + bh * 64 * D_;
    uint32_t* MlP = g_Ml + bh * 64 * D_;
#pragma unroll
    for (int a = 0; a < 8; a += 2)
#pragma unroll
        for (int b2 = 0; b2 < 8; b2++) {
            uint32_t hw, lw;
            packpair(acc[a][b2], acc[a + 1][b2], hw, lw);
            int m = (dg * 8 + a) >> 1;
            MhP[m * D_ + eg * 8 + b2] = hw;
            MlP[m * D_ + eg * 8 + b2] = lw;
        }
}

// ---------------- kernel 6: out += (phi_q @ M)/den + b ----------------
// 512 threads (16 warps, tile m16 x n32), 2 CTAs/SM, grid 256 (4 q-chunks/CTA).
__global__ void __launch_bounds__(512, 2)
k_lin_out(const float* __restrict__ q, const float* __restrict__ bias,
          float* __restrict__ out)
{
    extern __shared__ float sm[];
    uint32_t* Mh  = (uint32_t*)sm;            // 64*136 (d-pairs x d')
    uint32_t* Ml  = Mh + 64 * RPSTR;
    uint32_t* PHh = Ml + 64 * RPSTR;          // 64*68 (token rows x d-pairs)
    uint32_t* PHl = PHh + 64 * KPSTR;
    float* ksums  = (float*)(PHl + 64 * KPSTR);  // 128
    float* dens   = ksums + 128;                 // 64
    float* bs     = dens + 64;                   // 128

    const uint32_t PHhB = smem_u32(PHh);
    const uint32_t PHlB = PHhB + 64 * KPSTR * 4;

    int bh = blockIdx.x >> 3, cb0 = (blockIdx.x & 7) * 4;
    int tid = threadIdx.x, warp = tid >> 5, lane = tid & 31;
    int g = lane >> 2, t = lane & 3;
    int wm = warp >> 2, wn = warp & 3;         // 4x4 warps; tile m16 x n32

    // stage pre-packed M (plain u32 copies)
    for (int i = tid; i < 64 * 32; i += 512) {
        int m = i >> 5, dg = i & 31;
        uint4 hv = ((const uint4*)(g_Mh + bh * 64 * D_ + m * D_))[dg];
        uint4 lv = ((const uint4*)(g_Ml + bh * 64 * D_ + m * D_))[dg];
        *(uint4*)&Mh[m * RPSTR + 4 * dg] = hv;
        *(uint4*)&Ml[m * RPSTR + 4 * dg] = lv;
    }
    if (tid < 128) { ksums[tid] = g_ksum[bh * D_ + tid]; bs[tid] = bias[tid]; }

    const int r0 = wm * 16;
    uint32_t aAddr = (lane < 16 ? PHhB : PHlB) + (uint32_t)(r0 + (lane & 15)) * KPSTR * 4;

    for (int ch2 = 0; ch2 < 4; ch2++) {
        int cb = cb0 + ch2;
        const size_t base = (size_t)bh * L_ * D_ + (size_t)cb * 64 * D_;
        __syncthreads();   // M ready (ch0) / prev chunk's PH reads done
        // phi_q + den: warp w -> rows [w*4, w*4+4)
        for (int rr = 0; rr < 4; rr++) {
            int row = warp * 4 + rr;
            float4 a = ((const float4*)(q + base + (size_t)row * D_))[lane];
            float m = fmaxf(fmaxf(a.x, a.y), fmaxf(a.z, a.w));
#pragma unroll
            for (int o = 16; o > 0; o >>= 1) m = fmaxf(m, __shfl_xor_sync(0xffffffffu, m, o));
            float ex = __expf(a.x - m), ey = __expf(a.y - m);
            float ez = __expf(a.z - m), ew = __expf(a.w - m);
            float s = ex + ey + ez + ew;
#pragma unroll
            for (int o = 16; o > 0; o >>= 1) s += __shfl_xor_sync(0xffffffffu, s, o);
            float inv = 1.f / s;
            float px = ex * inv, py = ey * inv, pz = ez * inv, pw = ew * inv;
            uint32_t h0, l0, h1, l1;
            packpair(px, py, h0, l0);
            packpair(pz, pw, h1, l1);
            *(uint2*)&PHh[row * KPSTR + 2 * lane] = make_uint2(h0, h1);
            *(uint2*)&PHl[row * KPSTR + 2 * lane] = make_uint2(l0, l1);
            float4 ksv = ((const float4*)ksums)[lane];
            float dp = px*ksv.x + py*ksv.y + pz*ksv.z + pw*ksv.w;
#pragma unroll
            for (int o = 16; o > 0; o >>= 1) dp += __shfl_xor_sync(0xffffffffu, dp, o);
            if (lane == 0) dens[row] = 1e-5f + dp;
        }
        __syncthreads();

        float acc[4][4];
#pragma unroll
        for (int nt = 0; nt < 4; nt++)
#pragma unroll
            for (int c = 0; c < 4; c++) acc[nt][c] = 0.f;

#pragma unroll
        for (int ks = 0; ks < 16; ks++) {
            int pc = ks * 4 + t;
            uint32_t a0, a1, a2, a3;
            ldsm4(aAddr + ks * 16, a0, a1, a2, a3);
#pragma unroll
            for (int nt = 0; nt < 4; nt++) {
                int n = wn * 32 + nt * 8 + g;
                uint32_t bhw = Mh[pc * RPSTR + n];
                uint32_t blw = Ml[pc * RPSTR + n];
                mma16(acc[nt], a0, a1, a2, a3, bhw, blw);
                mma16(acc[nt], a0, a1, a2, a3, blw, bhw);
            }
        }

        float* op = out + base;
        int r = r0 + g;
        float inv0 = 1.f / dens[r];
        float inv1 = 1.f / dens[r + 8];
#pragma unroll
        for (int nt = 0; nt < 4; nt++) {
            int cc = wn * 32 + nt * 8 + 2 * t;
            float b0 = bs[cc], b1 = bs[cc + 1];
            float2 pr0 = *(float2*)&op[r * D_ + cc];
            pr0.x += acc[nt][0] * inv0 + b0;
            pr0.y += acc[nt][1] * inv0 + b1;
            *(float2*)&op[r * D_ + cc] = pr0;
            float2 pr1 = *(float2*)&op[(r + 8) * D_ + cc];
            pr1.x += acc[nt][2] * inv1 + b0;
            pr1.y += acc[nt][3] * inv1 + b1;
            *(float2*)&op[(r + 8) * D_ + cc] = pr1;
        }
    }
}

// ---------------- side stream + events (created once at static init) ----------------
struct StreamInit {
    cudaStream_t s1 = nullptr;
    cudaEvent_t  evFork = nullptr, evJoin = nullptr;
    bool ok = false;
    StreamInit() {
        int lo = 0, hi = 0;
        cudaDeviceGetStreamPriorityRange(&lo, &hi);   // lo = lowest priority
        if (cudaStreamCreateWithPriority(&s1, cudaStreamNonBlocking, lo) != cudaSuccess) return;
        if (cudaEventCreateWithFlags(&evFork, cudaEventDisableTiming) != cudaSuccess) return;
        if (cudaEventCreateWithFlags(&evJoin, cudaEventDisableTiming) != cudaSuccess) return;
        ok = true;
    }
};
static StreamInit g_si;

// ---------------- launch ----------------
extern "C" void kernel_launch(void* const* d_in, const int* in_sizes, int n_in,
                              void* d_out, int out_size)
{
    const float* q  = (const float*)d_in[0];
    const float* k  = (const float*)d_in[1];
    const float* v  = (const float*)d_in[2];
    const float* w  = (const float*)d_in[3];
    const float* bp = (const float*)d_in[4];
    float* out = (float*)d_out;

    const int sp_smem = (2*64*KPSTR + 2*4352 + 64*PSSTR + 512) * 4;     //  89600
    const int kv_smem = (4 * 32 * RPSTR) * 4;                           //  69632
    const int m_smem  = (2 * 128 * WSTR) * 4;                           // 135168
    const int lo_smem = (64*RPSTR*2 + 64*KPSTR*2 + 128 + 64 + 128) * 4; // 105728

    cudaFuncSetAttribute(k_sparse,  cudaFuncAttributeMaxDynamicSharedMemorySize, sp_smem);
    cudaFuncSetAttribute(k_kv,      cudaFuncAttributeMaxDynamicSharedMemorySize, kv_smem);
    cudaFuncSetAttribute(k_M,       cudaFuncAttributeMaxDynamicSharedMemorySize, m_smem);
    cudaFuncSetAttribute(k_lin_out, cudaFuncAttributeMaxDynamicSharedMemorySize, lo_smem);

    void* ksp = nullptr;
    cudaGetSymbolAddress(&ksp, g_ksum);

    if (g_si.ok) {
        // side (low prio): memset -> kv -> red -> M   (concurrent with main)
        // main: bm -> topk -> sparse; join; lin_out
        cudaEventRecord(g_si.evFork, 0);
        cudaStreamWaitEvent(g_si.s1, g_si.evFork, 0);

        k_blockmean<<<2048, 128>>>(q, k);
        k_topk<<<1024, 32>>>();
        k_sparse<<<1024, 512, sp_smem>>>(q, k, v, out);

        cudaMemsetAsync(ksp, 0, sizeof(float) * BH * D_, g_si.s1);
        k_kv<<<BH * NPART, 512, kv_smem, g_si.s1>>>(k, v);
        k_red<<<128, 256, 0, g_si.s1>>>();
        k_M<<<32, 256, m_smem, g_si.s1>>>(w);
        cudaEventRecord(g_si.evJoin, g_si.s1);

        cudaStreamWaitEvent(0, g_si.evJoin, 0);
        k_lin_out<<<256, 512, lo_smem>>>(q, bp, out);
    } else {
        cudaMemsetAsync(ksp, 0, sizeof(float) * BH * D_);
        k_blockmean<<<2048, 128>>>(q, k);
        k_topk<<<1024, 32>>>();
        k_kv<<<BH * NPART, 512, kv_smem>>>(k, v);
        k_sparse<<<1024, 512, sp_smem>>>(q, k, v, out);
        k_red<<<128, 256>>>();
        k_M<<<32, 256, m_smem>>>(w);
        k_lin_out<<<256, 512, lo_smem>>>(q, bp, out);
    }
}